// round 4
// baseline (speedup 1.0000x reference)
#include <cuda_runtime.h>
#include <cstdint>

// SM-2 spaced-repetition scan, warp-private double-buffered, high-occupancy.
// hist_p: [B, 400] f32 row-major. Block = 256 threads = 8 warps; each warp
// owns 32 rows and its own smem tiles. Chunk = 16 floats -> 40KB smem/block
// -> 5 blocks/SM (40 warps) with launch_bounds-capped 48 regs.
// 400 = 25 * 16: no tail path.

static constexpr int STEPS          = 400;
static constexpr int RPW            = 32;                  // rows per warp
static constexpr int WARPS          = 8;
static constexpr int ROWS_PER_BLOCK = RPW * WARPS;         // 256
static constexpr int CHUNK          = 16;                  // floats per chunk
static constexpr int NCHUNK         = STEPS / CHUNK;       // 25, exact
static constexpr int STRIDE         = CHUNK + 4;           // 20: conflict-free LDS.128
static constexpr int WBUF           = RPW * STRIDE;        // floats per stage per warp
static constexpr int SMEM_BYTES     = WARPS * 2 * WBUF * (int)sizeof(float); // 40960

__device__ __forceinline__ uint32_t smem_u32(const void* p) {
    return (uint32_t)__cvta_generic_to_shared(p);
}
__device__ __forceinline__ void cp_async16(uint32_t saddr, const void* gptr) {
    asm volatile("cp.async.cg.shared.global [%0], [%1], 16;\n" :: "r"(saddr), "l"(gptr));
}
__device__ __forceinline__ void cp_commit() {
    asm volatile("cp.async.commit_group;\n" ::: "memory");
}
template <int N>
__device__ __forceinline__ void cp_wait() {
    asm volatile("cp.async.wait_group %0;\n" :: "n"(N) : "memory");
}

// 13-op step; no per-step upper clamp on I (EF >= 1.3 keeps the product
// monotone within a correct-run; clamp once at output).
__device__ __forceinline__ void sm2_step(float p, float& I, float& EF, int& n) {
    bool correct = (p >= 0.6f);           // == (p*5 >= 3) in RN
    float IEF = I * EF;                   // old I, old EF
    n = correct ? (n + 1) : 0;
    I = (n >= 3) ? IEF : ((n == 2) ? 6.0f : 1.0f);
    float u   = fmaf(p, fmaf(p, -0.5f, 1.4f), -0.8f);  // 0.1-(5-5p)(0.08+(5-5p)*0.02)
    float EFn = fmaxf(EF + u, 1.3f);
    EF = correct ? EFn : EF;
}

extern __shared__ float sbuf[];

__global__ void __launch_bounds__(256, 5)
sm2_scan_kernel(const float* __restrict__ hist, float* __restrict__ out, int B) {
    const int lane  = threadIdx.x & 31;
    const int warp  = threadIdx.x >> 5;
    const int wrow0 = blockIdx.x * ROWS_PER_BLOCK + warp * RPW;

    float* buf0 = sbuf + warp * (2 * WBUF);
    float* buf1 = buf0 + WBUF;

    const float* g = hist + (size_t)wrow0 * STEPS;
    const bool full = (wrow0 + RPW <= B);

    // Chunk load: 32 rows x 16 floats. Iter s covers 8 rows; lanes give
    // 4 consecutive float4 per row -> 64B contiguous gmem per row segment.
    auto load_chunk = [&](float* buf, int c0) {
        #pragma unroll
        for (int s = 0; s < 4; s++) {
            int f = s * 32 + lane;
            int r = f >> 2, k = f & 3;
            if (full || wrow0 + r < B)
                cp_async16(smem_u32(buf + r * STRIDE + k * 4),
                           g + (size_t)r * STEPS + c0 + k * 4);
        }
    };

    float I = 1.0f, EF = 2.5f;
    int n = 0;

    load_chunk(buf0, 0);
    cp_commit();

    const bool live = full || (wrow0 + lane < B);

    #pragma unroll 1
    for (int c = 0; c < NCHUNK; c++) {
        float* cur = (c & 1) ? buf1 : buf0;
        float* nxt = (c & 1) ? buf0 : buf1;
        if (c + 1 < NCHUNK) {
            load_chunk(nxt, (c + 1) * CHUNK);
            cp_commit();
            cp_wait<1>();      // chunk c's group complete (this lane)
        } else {
            cp_wait<0>();      // last chunk
        }
        __syncwarp();          // make peer lanes' copies visible warp-wide

        if (live) {
            const float* m = cur + lane * STRIDE;
            #pragma unroll
            for (int j = 0; j < CHUNK / 4; j++) {
                float4 v = *reinterpret_cast<const float4*>(m + 4 * j);
                sm2_step(v.x, I, EF, n);
                sm2_step(v.y, I, EF, n);
                sm2_step(v.z, I, EF, n);
                sm2_step(v.w, I, EF, n);
            }
        }
        __syncwarp();          // protect cur before next iteration overwrites it
    }

    if (live)
        out[wrow0 + lane] = fminf(I, 274.0f);  // single deferred clamp; h_t = I
}

extern "C" void kernel_launch(void* const* d_in, const int* in_sizes, int n_in,
                              void* d_out, int out_size) {
    const float* hist = (const float*)d_in[0];
    float* out = (float*)d_out;
    int B = out_size;

    cudaFuncSetAttribute(sm2_scan_kernel,
                         cudaFuncAttributeMaxDynamicSharedMemorySize, SMEM_BYTES);

    int blocks = (B + ROWS_PER_BLOCK - 1) / ROWS_PER_BLOCK;
    sm2_scan_kernel<<<blocks, 256, SMEM_BYTES>>>(hist, out, B);
}

// round 5
// speedup vs baseline: 1.0842x; 1.0842x over previous
#include <cuda_runtime.h>
#include <cstdint>

// SM-2 scan, R-reformulated (no n counter) + packed f32x2, 2 rows/thread.
// hist_p: [B, 400] f32. Block = 128 threads = 4 warps; warp owns 64 rows
// (lane -> rows lane, lane+32). Double-buffered warp-private smem tiles.
//
// Recurrence reformulation (bit-exact vs reference below the 274 clamp):
//   R = I a correct answer would yield next step.
//   incorrect: I=1, R=1
//   correct:   I=R ; EF=max(EF+u,1.3) ; R = (R_old==1) ? 6 : I*EF
//   (R==1 is exact: product path always >= 1.3)
// Upper clamp deferred to output (EF>=1.3 keeps product monotone in a run).

static constexpr int STEPS          = 400;
static constexpr int RPW            = 64;                  // rows per warp
static constexpr int WARPS          = 4;
static constexpr int THREADS        = 32 * WARPS;          // 128
static constexpr int ROWS_PER_BLOCK = RPW * WARPS;         // 256
static constexpr int CHUNK          = 16;                  // floats per chunk
static constexpr int NCHUNK         = STEPS / CHUNK;       // 25 exact
static constexpr int STRIDE         = CHUNK + 4;           // 20: conflict-free LDS.128
static constexpr int WBUF           = RPW * STRIDE;        // 1280 floats
static constexpr int SMEM_BYTES     = WARPS * 2 * WBUF * (int)sizeof(float); // 40960

__device__ __forceinline__ uint32_t smem_u32(const void* p) {
    return (uint32_t)__cvta_generic_to_shared(p);
}
__device__ __forceinline__ void cp_async16(uint32_t saddr, const void* gptr) {
    asm volatile("cp.async.cg.shared.global [%0], [%1], 16;\n" :: "r"(saddr), "l"(gptr));
}
__device__ __forceinline__ void cp_commit() {
    asm volatile("cp.async.commit_group;\n" ::: "memory");
}
template <int N>
__device__ __forceinline__ void cp_wait() {
    asm volatile("cp.async.wait_group %0;\n" :: "n"(N) : "memory");
}

// Packed f32x2 helpers (sm_103a FFMA2/FMUL2/FADD2 via PTX).
union F2 { float2 v; float f[2]; unsigned long long u; };
__device__ __forceinline__ F2 mk2(float a, float b) { F2 r; r.f[0] = a; r.f[1] = b; return r; }
__device__ __forceinline__ F2 mul2(F2 a, F2 b) {
    F2 d; asm("mul.rn.f32x2 %0, %1, %2;" : "=l"(d.u) : "l"(a.u), "l"(b.u)); return d;
}
__device__ __forceinline__ F2 add2(F2 a, F2 b) {
    F2 d; asm("add.rn.f32x2 %0, %1, %2;" : "=l"(d.u) : "l"(a.u), "l"(b.u)); return d;
}
__device__ __forceinline__ F2 fma2(F2 a, F2 b, F2 c) {
    F2 d; asm("fma.rn.f32x2 %0, %1, %2, %3;" : "=l"(d.u) : "l"(a.u), "l"(b.u), "l"(c.u)); return d;
}

// One step for two independent rows. ~18 SASS ops.
__device__ __forceinline__ void sm2_step2(float pa, float pb, F2& I, F2& EF, F2& R) {
    const bool ca = pa >= 0.6f;          // == (p*5 >= 3) in RN
    const bool cb = pb >= 0.6f;

    float Ia = ca ? R.f[0] : 1.0f;
    float Ib = cb ? R.f[1] : 1.0f;

    F2 p = mk2(pa, pb);
    F2 w = fma2(p, mk2(-0.5f, -0.5f), mk2(1.4f, 1.4f));
    F2 u = fma2(p, w, mk2(-0.8f, -0.8f));      // 0.1-(5-5p)(0.08+(5-5p)*0.02)
    F2 EFn = add2(EF, u);
    EFn.f[0] = fmaxf(EFn.f[0], 1.3f);
    EFn.f[1] = fmaxf(EFn.f[1], 1.3f);
    EF.f[0] = ca ? EFn.f[0] : EF.f[0];
    EF.f[1] = cb ? EFn.f[1] : EF.f[1];

    I = mk2(Ia, Ib);
    F2 t = mul2(I, EF);                        // I*EF with next step's entry values
    R.f[0] = ca ? ((R.f[0] == 1.0f) ? 6.0f : t.f[0]) : 1.0f;
    R.f[1] = cb ? ((R.f[1] == 1.0f) ? 6.0f : t.f[1]) : 1.0f;
}

extern __shared__ float sbuf[];

__global__ void __launch_bounds__(THREADS, 5)
sm2_scan_kernel(const float* __restrict__ hist, float* __restrict__ out, int B) {
    const int lane  = threadIdx.x & 31;
    const int warp  = threadIdx.x >> 5;
    const int wrow0 = blockIdx.x * ROWS_PER_BLOCK + warp * RPW;

    float* buf0 = sbuf + warp * (2 * WBUF);
    float* buf1 = buf0 + WBUF;

    const float* g = hist + (size_t)wrow0 * STEPS;
    const bool full = (wrow0 + RPW <= B);

    // Chunk load: 64 rows x 16 floats; iter s covers 8 rows, 4 f4/row
    // (64B contiguous gmem per row segment).
    auto load_chunk = [&](float* buf, int c0) {
        #pragma unroll
        for (int s = 0; s < 8; s++) {
            int f = s * 32 + lane;
            int r = f >> 2, k = f & 3;
            if (full || wrow0 + r < B)
                cp_async16(smem_u32(buf + r * STRIDE + k * 4),
                           g + (size_t)r * STEPS + c0 + k * 4);
        }
    };

    F2 I  = mk2(1.0f, 1.0f);
    F2 EF = mk2(2.5f, 2.5f);
    F2 R  = mk2(1.0f, 1.0f);

    load_chunk(buf0, 0);
    cp_commit();

    const int ra = lane, rb = lane + 32;
    const bool livea = full || (wrow0 + ra < B);
    const bool liveb = full || (wrow0 + rb < B);

    #pragma unroll 1
    for (int c = 0; c < NCHUNK; c++) {
        float* cur = (c & 1) ? buf1 : buf0;
        float* nxt = (c & 1) ? buf0 : buf1;
        if (c + 1 < NCHUNK) {
            load_chunk(nxt, (c + 1) * CHUNK);
            cp_commit();
            cp_wait<1>();      // chunk c complete (this lane's copies)
        } else {
            cp_wait<0>();
        }
        __syncwarp();          // peer lanes' copies visible warp-wide

        const float* ma = cur + ra * STRIDE;
        const float* mb = cur + rb * STRIDE;
        #pragma unroll
        for (int j = 0; j < CHUNK / 4; j++) {
            float4 va = *reinterpret_cast<const float4*>(ma + 4 * j);
            float4 vb = *reinterpret_cast<const float4*>(mb + 4 * j);
            sm2_step2(va.x, vb.x, I, EF, R);
            sm2_step2(va.y, vb.y, I, EF, R);
            sm2_step2(va.z, vb.z, I, EF, R);
            sm2_step2(va.w, vb.w, I, EF, R);
        }
        __syncwarp();          // protect cur before it is overwritten
    }

    if (livea) out[wrow0 + ra] = fminf(I.f[0], 274.0f);  // h_t = I, deferred clamp
    if (liveb) out[wrow0 + rb] = fminf(I.f[1], 274.0f);
}

extern "C" void kernel_launch(void* const* d_in, const int* in_sizes, int n_in,
                              void* d_out, int out_size) {
    const float* hist = (const float*)d_in[0];
    float* out = (float*)d_out;
    int B = out_size;

    cudaFuncSetAttribute(sm2_scan_kernel,
                         cudaFuncAttributeMaxDynamicSharedMemorySize, SMEM_BYTES);

    int blocks = (B + ROWS_PER_BLOCK - 1) / ROWS_PER_BLOCK;
    sm2_scan_kernel<<<blocks, THREADS, SMEM_BYTES>>>(hist, out, B);
}